// round 1
// baseline (speedup 1.0000x reference)
#include <cuda_runtime.h>
#include <cstdint>
#include <math.h>

#define DD     5
#define HGRID  24
#define WGRID  48
#define CLV    1024
#define NB     4
#define DIM    128
#define LMAX   12
#define DEPTH  6
#define LTOK   16
#define BALL   (DD*HGRID*WGRID)   // 5760
#define CAP    64
#define G      4
#define RROWS  (G*LTOK)           // 64
#define NT     256

// ---------------- device scratch (static, allowed) ----------------
__device__ int   g_counts[BALL];
__device__ int   g_list[BALL*CAP];
__device__ float g_bgp[NB*DIM];
__device__ float g_feat[BALL*NB*DIM];   // per-cell 512-vector for final proj

// ---------------- packed f32x2 helpers ----------------
__device__ __forceinline__ unsigned long long pk2(float lo, float hi){
    unsigned long long r;
    asm("mov.b64 %0,{%1,%2};" : "=l"(r) : "f"(lo), "f"(hi));
    return r;
}
__device__ __forceinline__ void upk2(unsigned long long v, float &lo, float &hi){
    asm("mov.b64 {%0,%1},%2;" : "=f"(lo), "=f"(hi) : "l"(v));
}
__device__ __forceinline__ unsigned long long fma2(unsigned long long a,
                                                   unsigned long long b,
                                                   unsigned long long c){
    unsigned long long d;
    asm("fma.rn.f32x2 %0,%1,%2,%3;" : "=l"(d) : "l"(a), "l"(b), "l"(c));
    return d;
}

__device__ __forceinline__ float gelu_f(float x){
    float x3 = x*x*x;
    return 0.5f*x*(1.0f + tanhf(0.7978845608028654f*(x + 0.044715f*x3)));
}

// ---------------- tiny setup kernels ----------------
__global__ void k_zero(){
    int i = blockIdx.x*blockDim.x + threadIdx.x;
    if (i < BALL) g_counts[i] = 0;
}

__global__ void k_scatter(const int* __restrict__ li, int n){
    int i = blockIdx.x*blockDim.x + threadIdx.x;
    if (i >= n) return;
    int a = li[3*i], b = li[3*i+1], c = li[3*i+2];
    int flat = a*(HGRID*WGRID) + b*WGRID + c;
    int slot = atomicAdd(&g_counts[flat], 1);
    if (slot < CAP) g_list[flat*CAP + slot] = i;
}

// background + direct projection (constant across cells)
__global__ void k_bg(const float* __restrict__ ob,
                     const float* __restrict__ dw,
                     const float* __restrict__ db){
    int c = blockIdx.x*blockDim.x + threadIdx.x;   // 0..511
    if (c >= NB*DIM) return;
    float s = 0.0f;
    for (int m = 0; m < NB; m++){
        const float* bg = ob + m*DIM;
        float t = 0.0f;
        for (int k = 0; k < DIM; k++)
            t += bg[k] * dw[k*(NB*DIM) + c];
        s += t;
    }
    s = s * (1.0f/NB) + db[c];
    g_bgp[c] = ob[c] + s;   // ob is (NB,DIM) row-major, c = j*128+d
}

// ---------------- GEMM panel: C(64 x 64) = A(64 x K) * B(K x 64) ----------------
// A in smem (row-major, lda). B from global (row-major, ldb), staged into Bs.
// MODE: 0=zero init, 1=bias init, 2=load C (accumulate), 3=load C + bias.
template<int K, int MODE, bool DOGELU>
__device__ __forceinline__ void gemm_panel(const float* __restrict__ A, int lda,
                                           const float* __restrict__ Bg, int ldb,
                                           const float* __restrict__ bias,
                                           float* __restrict__ C, int ldc,
                                           float* __restrict__ Bs){
    const int tid = threadIdx.x;
    // stage B panel: Bs[k][c], K x 64
    #pragma unroll 4
    for (int i = tid; i < K*64; i += NT){
        int k = i >> 6, c = i & 63;
        Bs[i] = Bg[k*ldb + c];
    }
    __syncthreads();

    const int cg = tid & 15, rg = tid >> 4;
    const int r0 = rg*4, c0 = cg*4;

    unsigned long long acc[4][2];
    if (MODE == 0){
        #pragma unroll
        for (int i = 0; i < 4; i++){ acc[i][0] = 0ull; acc[i][1] = 0ull; }
    } else if (MODE == 1){
        unsigned long long b01 = pk2(bias[c0+0], bias[c0+1]);
        unsigned long long b23 = pk2(bias[c0+2], bias[c0+3]);
        #pragma unroll
        for (int i = 0; i < 4; i++){ acc[i][0] = b01; acc[i][1] = b23; }
    } else {
        float bb0=0.f, bb1=0.f, bb2=0.f, bb3=0.f;
        if (MODE == 3){ bb0=bias[c0+0]; bb1=bias[c0+1]; bb2=bias[c0+2]; bb3=bias[c0+3]; }
        #pragma unroll
        for (int i = 0; i < 4; i++){
            float4 cv = *(const float4*)(C + (r0+i)*ldc + c0);
            acc[i][0] = pk2(cv.x + bb0, cv.y + bb1);
            acc[i][1] = pk2(cv.z + bb2, cv.w + bb3);
        }
    }

    #pragma unroll 2
    for (int k = 0; k < K; k += 4){
        float4 av[4];
        #pragma unroll
        for (int i = 0; i < 4; i++)
            av[i] = *(const float4*)(A + (r0+i)*lda + k);
        #pragma unroll
        for (int kk = 0; kk < 4; kk++){
            ulonglong2 bb = *(const ulonglong2*)(Bs + (k+kk)*64 + c0);
            #pragma unroll
            for (int i = 0; i < 4; i++){
                float a = ((const float*)&av[i])[kk];
                unsigned long long pa = pk2(a, a);
                acc[i][0] = fma2(pa, bb.x, acc[i][0]);
                acc[i][1] = fma2(pa, bb.y, acc[i][1]);
            }
        }
    }

    #pragma unroll
    for (int i = 0; i < 4; i++){
        float f0,f1,f2,f3;
        upk2(acc[i][0], f0, f1);
        upk2(acc[i][1], f2, f3);
        if (DOGELU){ f0=gelu_f(f0); f1=gelu_f(f1); f2=gelu_f(f2); f3=gelu_f(f3); }
        *(float4*)(C + (r0+i)*ldc + c0) = make_float4(f0,f1,f2,f3);
    }
    __syncthreads();
}

// ---------------- row LayerNorm: dst = LN(src)*w + b, rows = RROWS ----------------
__device__ __forceinline__ void layernorm(const float* __restrict__ src,
                                          float* __restrict__ dst,
                                          const float* __restrict__ w,
                                          const float* __restrict__ b){
    const int warp = threadIdx.x >> 5, lane = threadIdx.x & 31;
    for (int r = warp; r < RROWS; r += NT/32){
        float4 v = *(const float4*)(src + r*DIM + lane*4);
        float s  = v.x+v.y+v.z+v.w;
        float ss = v.x*v.x+v.y*v.y+v.z*v.z+v.w*v.w;
        #pragma unroll
        for (int o = 16; o; o >>= 1){
            s  += __shfl_xor_sync(0xffffffffu, s,  o);
            ss += __shfl_xor_sync(0xffffffffu, ss, o);
        }
        float mean = s * (1.0f/DIM);
        float var  = ss * (1.0f/DIM) - mean*mean;
        float rstd = rsqrtf(var + 1e-5f);
        float4 wv = *(const float4*)(w + lane*4);
        float4 bv = *(const float4*)(b + lane*4);
        float4 o4;
        o4.x = (v.x-mean)*rstd*wv.x + bv.x;
        o4.y = (v.y-mean)*rstd*wv.y + bv.y;
        o4.z = (v.z-mean)*rstd*wv.z + bv.z;
        o4.w = (v.w-mean)*rstd*wv.w + bv.w;
        *(float4*)(dst + r*DIM + lane*4) = o4;
    }
}

// ---------------- fused per-4-cell transformer ----------------
__global__ __launch_bounds__(NT, 1)
void k_transformer(const float* __restrict__ x,
                   const float* __restrict__ ln1w, const float* __restrict__ ln1b,
                   const float* __restrict__ wqkv, const float* __restrict__ bqkv,
                   const float* __restrict__ wo,   const float* __restrict__ bo,
                   const float* __restrict__ ln2w, const float* __restrict__ ln2b,
                   const float* __restrict__ w1,   const float* __restrict__ b1,
                   const float* __restrict__ w2,   const float* __restrict__ b2){
    extern __shared__ float smem[];
    float* sh  = smem;                  // RROWS*DIM
    float* sxn = sh  + RROWS*DIM;       // RROWS*DIM
    float* sq  = sxn + RROWS*DIM;       // RROWS*64  (also O and MLP tile)
    float* sk  = sq  + RROWS*64;
    float* sv  = sk  + RROWS*64;
    float* sb  = sv  + RROWS*64;        // 128*64 weight stage
    int*  sel   = (int*)(sb + 128*64);  // G*LMAX
    int*  smcnt = sel + G*LMAX;         // G

    const int tid   = threadIdx.x;
    const int cell0 = blockIdx.x * G;

    // ---- token assembly ----
    if (tid < G){
        int cell  = cell0 + tid;
        int cnt   = g_counts[cell];
        int avail = min(cnt, CAP);
        int m     = min(cnt, LMAX);
        smcnt[tid] = m;
        if (cnt <= LMAX){
            for (int j = 0; j < m; j++)
                sel[tid*LMAX + j] = g_list[cell*CAP + j];
        } else {
            // keep the LMAX smallest original indices (matches stable argsort)
            int tmp[CAP];
            for (int j = 0; j < avail; j++) tmp[j] = g_list[cell*CAP + j];
            for (int a = 0; a < m; a++){
                int best = a;
                for (int bq = a+1; bq < avail; bq++)
                    if (tmp[bq] < tmp[best]) best = bq;
                int t2 = tmp[best]; tmp[best] = tmp[a]; tmp[a] = t2;
                sel[tid*LMAX + a] = t2;
            }
        }
    }
    __syncthreads();

    for (int i = tid; i < RROWS*DIM; i += NT){
        int r = i >> 7, d = i & 127;
        int g = r >> 4, lr = r & 15;
        float v;
        if (lr < NB) v = g_bgp[lr*DIM + d];
        else {
            int j = lr - NB;
            v = (j < smcnt[g]) ? x[(size_t)sel[g*LMAX + j]*DIM + d] : 0.0f;
        }
        sh[i] = v;
    }
    __syncthreads();

    const float scale = 0.17677669529663687f;   // 1/sqrt(32)

    for (int layer = 0; layer < DEPTH; layer++){
        // ---- attention block ----
        layernorm(sh, sxn, ln1w + layer*DIM, ln1b + layer*DIM);
        __syncthreads();

        const float* wq = wqkv + (size_t)layer*DIM*3*DIM;
        const float* bq = bqkv + layer*3*DIM;

        for (int p = 0; p < 2; p++){                  // head pairs
            gemm_panel<128,1,false>(sxn, DIM, wq +       p*64, 3*DIM, bq +       p*64, sq, 64, sb);
            gemm_panel<128,1,false>(sxn, DIM, wq + 128 + p*64, 3*DIM, bq + 128 + p*64, sk, 64, sb);
            gemm_panel<128,1,false>(sxn, DIM, wq + 256 + p*64, 3*DIM, bq + 256 + p*64, sv, 64, sb);

            // attention: 64 token rows x 2 heads = 128 units
            if (tid < 128){
                int row = tid & 63;
                int hp  = tid >> 6;
                int g   = row >> 4;
                const float* qp = sq + row*64 + hp*32;
                float q[32];
                #pragma unroll
                for (int i = 0; i < 32; i++) q[i] = qp[i];
                float sc[16]; float mx = -1e30f;
                #pragma unroll
                for (int j = 0; j < 16; j++){
                    const float* kp = sk + (g*16 + j)*64 + hp*32;
                    float s = 0.0f;
                    #pragma unroll
                    for (int i = 0; i < 32; i++) s += q[i]*kp[i];
                    s *= scale;
                    sc[j] = s; mx = fmaxf(mx, s);
                }
                float den = 0.0f;
                #pragma unroll
                for (int j = 0; j < 16; j++){ sc[j] = expf(sc[j]-mx); den += sc[j]; }
                float inv = 1.0f/den;
                float o[32];
                #pragma unroll
                for (int i = 0; i < 32; i++) o[i] = 0.0f;
                #pragma unroll
                for (int j = 0; j < 16; j++){
                    float pj = sc[j]*inv;
                    const float* vp = sv + (g*16 + j)*64 + hp*32;
                    #pragma unroll
                    for (int i = 0; i < 32; i++) o[i] += pj*vp[i];
                }
                float* op = sq + row*64 + hp*32;   // overwrite own Q slot with O
                #pragma unroll
                for (int i = 0; i < 32; i++) op[i] = o[i];
            }
            __syncthreads();

            // h += O @ wo[p*64 .. p*64+63, :]  (+ bo once)
            for (int cp = 0; cp < 2; cp++){
                const float* wop = wo + (size_t)layer*DIM*DIM + (p*64)*DIM + cp*64;
                if (p == 0)
                    gemm_panel<64,3,false>(sq, 64, wop, DIM, bo + layer*DIM + cp*64, sh + cp*64, DIM, sb);
                else
                    gemm_panel<64,2,false>(sq, 64, wop, DIM, (const float*)0,       sh + cp*64, DIM, sb);
            }
        }

        // ---- MLP block ----
        layernorm(sh, sxn, ln2w + layer*DIM, ln2b + layer*DIM);
        __syncthreads();

        for (int n = 0; n < 8; n++){    // 8 panels of 64 over the 512 hidden
            gemm_panel<128,1,true>(sxn, DIM, w1 + (size_t)layer*DIM*512 + n*64, 512,
                                   b1 + layer*512 + n*64, sq, 64, sb);
            for (int cp = 0; cp < 2; cp++){
                const float* w2p = w2 + (size_t)layer*512*DIM + (n*64)*DIM + cp*64;
                if (n == 0)
                    gemm_panel<64,3,false>(sq, 64, w2p, DIM, b2 + layer*DIM + cp*64, sh + cp*64, DIM, sb);
                else
                    gemm_panel<64,2,false>(sq, 64, w2p, DIM, (const float*)0,       sh + cp*64, DIM, sb);
            }
        }
    }

    // ---- write background features for final projection ----
    for (int i = tid; i < G*NB*DIM; i += NT){
        int g   = i >> 9;
        int rem = i & 511;
        int lr  = rem >> 7;
        int d   = rem & 127;
        g_feat[(size_t)(cell0+g)*(NB*DIM) + rem] = sh[(g*LTOK + lr)*DIM + d];
    }
}

// ---------------- final projection: out(5760 x 1024) = feat(5760 x 512) @ W + b ----------------
__global__ __launch_bounds__(NT, 2)
void k_proj(const float* __restrict__ Wp, const float* __restrict__ bp,
            float* __restrict__ out){
    __shared__ float As[64*64];
    __shared__ float Bs[64*64];
    const int tid = threadIdx.x;
    const int rowblk = blockIdx.x, colblk = blockIdx.y;
    const int cg = tid & 15, rg = tid >> 4;
    const int r0 = rg*4, c0 = cg*4;

    unsigned long long acc[4][2];
    {
        const float* bb = bp + colblk*64 + c0;
        unsigned long long b01 = pk2(bb[0], bb[1]);
        unsigned long long b23 = pk2(bb[2], bb[3]);
        #pragma unroll
        for (int i = 0; i < 4; i++){ acc[i][0] = b01; acc[i][1] = b23; }
    }

    for (int kt = 0; kt < 8; kt++){
        for (int i = tid; i < 64*64; i += NT){
            int r = i >> 6, c = i & 63;
            As[i] = g_feat[(size_t)(rowblk*64 + r)*(NB*DIM) + kt*64 + c];
            Bs[i] = Wp[(size_t)(kt*64 + r)*CLV + colblk*64 + c];
        }
        __syncthreads();
        #pragma unroll 2
        for (int k = 0; k < 64; k += 4){
            float4 av[4];
            #pragma unroll
            for (int i = 0; i < 4; i++)
                av[i] = *(const float4*)(As + (r0+i)*64 + k);
            #pragma unroll
            for (int kk = 0; kk < 4; kk++){
                ulonglong2 bb = *(const ulonglong2*)(Bs + (k+kk)*64 + c0);
                #pragma unroll
                for (int i = 0; i < 4; i++){
                    float a = ((const float*)&av[i])[kk];
                    unsigned long long pa = pk2(a, a);
                    acc[i][0] = fma2(pa, bb.x, acc[i][0]);
                    acc[i][1] = fma2(pa, bb.y, acc[i][1]);
                }
            }
        }
        __syncthreads();
    }

    #pragma unroll
    for (int i = 0; i < 4; i++){
        int cell = rowblk*64 + r0 + i;
        bool present = (g_counts[cell] > 0);
        float f0,f1,f2,f3;
        upk2(acc[i][0], f0, f1);
        upk2(acc[i][1], f2, f3);
        float4 o = present ? make_float4(f0,f1,f2,f3) : make_float4(0.f,0.f,0.f,0.f);
        *(float4*)(out + (size_t)cell*CLV + colblk*64 + c0) = o;
    }
}

// ---------------- launch ----------------
extern "C" void kernel_launch(void* const* d_in, const int* in_sizes, int n_in,
                              void* d_out, int out_size){
    const float* x    = (const float*)d_in[0];
    const int*   li   = (const int*)  d_in[1];
    const float* ob   = (const float*)d_in[2];
    const float* dw   = (const float*)d_in[3];
    const float* db   = (const float*)d_in[4];
    const float* ln1w = (const float*)d_in[5];
    const float* ln1b = (const float*)d_in[6];
    const float* wqkv = (const float*)d_in[7];
    const float* bqkv = (const float*)d_in[8];
    const float* wo   = (const float*)d_in[9];
    const float* bo   = (const float*)d_in[10];
    const float* ln2w = (const float*)d_in[11];
    const float* ln2b = (const float*)d_in[12];
    const float* w1   = (const float*)d_in[13];
    const float* b1   = (const float*)d_in[14];
    const float* w2   = (const float*)d_in[15];
    const float* b2   = (const float*)d_in[16];
    const float* pw   = (const float*)d_in[17];
    const float* pb   = (const float*)d_in[18];

    int n = in_sizes[0] / DIM;

    const int SMEM_BYTES = (2*RROWS*DIM + 3*RROWS*64 + 128*64) * 4 + (G*LMAX + G) * 4;
    cudaFuncSetAttribute(k_transformer, cudaFuncAttributeMaxDynamicSharedMemorySize, SMEM_BYTES);

    k_zero<<<(BALL + 255)/256, 256>>>();
    k_scatter<<<(n + 255)/256, 256>>>(li, n);
    k_bg<<<2, 256>>>(ob, dw, db);
    k_transformer<<<BALL/G, NT, SMEM_BYTES>>>(x, ln1w, ln1b, wqkv, bqkv, wo, bo,
                                              ln2w, ln2b, w1, b1, w2, b2);
    k_proj<<<dim3(BALL/64, CLV/64), NT>>>(pw, pb, (float*)d_out);
}